// round 1
// baseline (speedup 1.0000x reference)
#include <cuda_runtime.h>

// Divergence of (average(M) * gradient(mu)) with periodic boundaries.
// Shapes: (B=16, C=1, H=1024, W=1024) fp32.
// out[p] = sum_ax [ v_ax(p) - v_ax(p - e_ax) ],  v_ax(p) = 0.5*(M[p+e]+M[p])*(mu[p+e]-mu[p])
//
// One thread per float4 along W. 5-point stencil; vertical neighbors re-read
// through L2, horizontal halo via 2 wrap-aware scalar loads.

#define H_DIM 1024
#define W_DIM 1024
#define N_IMG 16
#define W4 (W_DIM / 4)   // 256 float4 per row

__global__ __launch_bounds__(256) void div_grad_kernel(
    const float* __restrict__ M,
    const float* __restrict__ mu,
    float* __restrict__ out)
{
    int idx = blockIdx.x * blockDim.x + threadIdx.x;
    // idx layout: [img (4b)][h (10b)][w4 (8b)] ; total = 16*1024*256 = 2^22 threads
    int w4  = idx & (W4 - 1);
    int h   = (idx >> 8) & (H_DIM - 1);
    int img = idx >> 18;

    const size_t imgOff = (size_t)img * H_DIM * W_DIM;
    const int hp = (h + 1) & (H_DIM - 1);
    const int hm = (h - 1) & (H_DIM - 1);

    const float* Mc  = M  + imgOff + (size_t)h  * W_DIM;
    const float* Md  = M  + imgOff + (size_t)hp * W_DIM;
    const float* Mu_ = M  + imgOff + (size_t)hm * W_DIM;
    const float* uc  = mu + imgOff + (size_t)h  * W_DIM;
    const float* ud  = mu + imgOff + (size_t)hp * W_DIM;
    const float* uu  = mu + imgOff + (size_t)hm * W_DIM;

    const int wbase = w4 << 2;

    // Center vectors
    float4 mC = *reinterpret_cast<const float4*>(Mc + wbase);
    float4 uC = *reinterpret_cast<const float4*>(uc + wbase);
    // Vertical neighbors
    float4 mD = *reinterpret_cast<const float4*>(Md + wbase);
    float4 uD = *reinterpret_cast<const float4*>(ud + wbase);
    float4 mU = *reinterpret_cast<const float4*>(Mu_ + wbase);
    float4 uU = *reinterpret_cast<const float4*>(uu + wbase);

    // Horizontal halo (wrap within the 1024-wide row)
    const int wL = (wbase - 1) & (W_DIM - 1);
    const int wR = (wbase + 4) & (W_DIM - 1);
    float mLft = Mc[wL];
    float uLft = uc[wL];
    float mRgt = Mc[wR];
    float uRgt = uc[wR];

    // Unpack into arrays for per-element work
    float mc[6], um[6];  // index 0 = left halo, 1..4 = center, 5 = right halo
    mc[0] = mLft; mc[1] = mC.x; mc[2] = mC.y; mc[3] = mC.z; mc[4] = mC.w; mc[5] = mRgt;
    um[0] = uLft; um[1] = uC.x; um[2] = uC.y; um[3] = uC.z; um[4] = uC.w; um[5] = uRgt;

    float md[4] = {mD.x, mD.y, mD.z, mD.w};
    float udn[4] = {uD.x, uD.y, uD.z, uD.w};
    float mup[4] = {mU.x, mU.y, mU.z, mU.w};
    float uup[4] = {uU.x, uU.y, uU.z, uU.w};

    float4 res;
    float* r = &res.x;
    #pragma unroll
    for (int e = 0; e < 4; ++e) {
        const float mCe = mc[e + 1], uCe = um[e + 1];
        // W direction: forward flux at p, backward flux at p (flux at p - e_w)
        float vWf = 0.5f * (mc[e + 2] + mCe) * (um[e + 2] - uCe);
        float vWb = 0.5f * (mCe + mc[e])     * (uCe - um[e]);
        // H direction
        float vHf = 0.5f * (md[e]  + mCe) * (udn[e] - uCe);
        float vHb = 0.5f * (mCe + mup[e]) * (uCe - uup[e]);
        r[e] = (vWf - vWb) + (vHf - vHb);
    }

    *reinterpret_cast<float4*>(out + imgOff + (size_t)h * W_DIM + wbase) = res;
}

extern "C" void kernel_launch(void* const* d_in, const int* in_sizes, int n_in,
                              void* d_out, int out_size)
{
    const float* M  = (const float*)d_in[0];
    const float* mu = (const float*)d_in[1];
    float* out = (float*)d_out;

    const int total_threads = N_IMG * H_DIM * W4;  // 4,194,304
    const int block = 256;
    const int grid = total_threads / block;        // 16,384
    div_grad_kernel<<<grid, block>>>(M, mu, out);
}

// round 3
// speedup vs baseline: 1.1119x; 1.1119x over previous
#include <cuda_runtime.h>

// Divergence of (average(M) * gradient(mu)) with periodic boundaries.
// Shapes: (B=16, C=1, H=1024, W=1024) fp32.
// out[p] = sum_ax [ v_ax(p) - v_ax(p - e_ax) ],  v_ax(p) = 0.5*(M[p+e]+M[p])*(mu[p+e]-mu[p])
//
// Each thread produces a 2(row) x 4(col float4) patch. Vertical neighbors are
// shared across the two rows (8 float4 loads per thread total). Horizontal
// halos come from warp shuffles; only lane 0 / lane 31 load one wrap-aware
// scalar per row per array (issued early, overlapped with vector loads).

#define H_DIM 1024
#define W_DIM 1024
#define N_IMG 16
#define W4 256            // float4 per row

__device__ __forceinline__ float4 row_result(
    const float4 m, const float4 u,
    float mL, float uL, float mR, float uR,
    const float4 mup, const float4 uup,
    const float4 mdn, const float4 udn)
{
    // W-direction forward fluxes (vWb[e] == vWf[e-1])
    float vm = 0.5f * (m.x + mL)  * (u.x - uL);
    float v0 = 0.5f * (m.y + m.x) * (u.y - u.x);
    float v1 = 0.5f * (m.z + m.y) * (u.z - u.y);
    float v2 = 0.5f * (m.w + m.z) * (u.w - u.z);
    float v3 = 0.5f * (mR  + m.w) * (uR  - u.w);

    float4 r;
    r.x = (v0 - vm) + 0.5f * (mdn.x + m.x) * (udn.x - u.x) - 0.5f * (m.x + mup.x) * (u.x - uup.x);
    r.y = (v1 - v0) + 0.5f * (mdn.y + m.y) * (udn.y - u.y) - 0.5f * (m.y + mup.y) * (u.y - uup.y);
    r.z = (v2 - v1) + 0.5f * (mdn.z + m.z) * (udn.z - u.z) - 0.5f * (m.z + mup.z) * (u.z - uup.z);
    r.w = (v3 - v2) + 0.5f * (mdn.w + m.w) * (udn.w - u.w) - 0.5f * (m.w + mup.w) * (u.w - uup.w);
    return r;
}

__global__ __launch_bounds__(256) void div_grad_kernel(
    const float* __restrict__ M,
    const float* __restrict__ mu,
    float* __restrict__ out)
{
    const int w4   = threadIdx.x;          // 0..255  (one block = one row-pair)
    const int lane = threadIdx.x & 31;
    const int rp   = blockIdx.x & 511;     // row-pair index
    const int img  = blockIdx.x >> 9;

    const int h0 = rp << 1;                // even, 0..1022
    const int h1 = h0 + 1;                 // odd, never wraps
    const int hm = (h0 - 1) & (H_DIM - 1);
    const int h2 = (h0 + 2) & (H_DIM - 1);

    const size_t base = (size_t)img << 20; // 1024*1024 elements per image
    const float* Mi = M  + base;
    const float* Ui = mu + base;

    const int wb = w4 << 2;

    const float* Mrm = Mi + ((size_t)hm << 10);
    const float* Mr0 = Mi + ((size_t)h0 << 10);
    const float* Mr1 = Mi + ((size_t)h1 << 10);
    const float* Mr2 = Mi + ((size_t)h2 << 10);
    const float* Urm = Ui + ((size_t)hm << 10);
    const float* Ur0 = Ui + ((size_t)h0 << 10);
    const float* Ur1 = Ui + ((size_t)h1 << 10);
    const float* Ur2 = Ui + ((size_t)h2 << 10);

    // Boundary-lane halo loads issued FIRST so they overlap the vector loads.
    float bM0 = 0.f, bU0 = 0.f, bM1 = 0.f, bU1 = 0.f;
    if (lane == 0) {
        const int wl = (wb - 1) & (W_DIM - 1);
        bM0 = Mr0[wl]; bU0 = Ur0[wl];
        bM1 = Mr1[wl]; bU1 = Ur1[wl];
    } else if (lane == 31) {
        const int wr = (wb + 4) & (W_DIM - 1);
        bM0 = Mr0[wr]; bU0 = Ur0[wr];
        bM1 = Mr1[wr]; bU1 = Ur1[wr];
    }

    // 8 independent vector loads (max MLP)
    float4 mMm = *reinterpret_cast<const float4*>(Mrm + wb);
    float4 m0  = *reinterpret_cast<const float4*>(Mr0 + wb);
    float4 m1  = *reinterpret_cast<const float4*>(Mr1 + wb);
    float4 m2  = *reinterpret_cast<const float4*>(Mr2 + wb);
    float4 uMm = *reinterpret_cast<const float4*>(Urm + wb);
    float4 u0  = *reinterpret_cast<const float4*>(Ur0 + wb);
    float4 u1  = *reinterpret_cast<const float4*>(Ur1 + wb);
    float4 u2  = *reinterpret_cast<const float4*>(Ur2 + wb);

    // Horizontal halos via shuffle; boundary lanes substitute their loads.
    const unsigned FULL = 0xffffffffu;
    float lM0 = __shfl_up_sync(FULL, m0.w, 1);
    float lU0 = __shfl_up_sync(FULL, u0.w, 1);
    float lM1 = __shfl_up_sync(FULL, m1.w, 1);
    float lU1 = __shfl_up_sync(FULL, u1.w, 1);
    float rM0 = __shfl_down_sync(FULL, m0.x, 1);
    float rU0 = __shfl_down_sync(FULL, u0.x, 1);
    float rM1 = __shfl_down_sync(FULL, m1.x, 1);
    float rU1 = __shfl_down_sync(FULL, u1.x, 1);

    if (lane == 0) {
        lM0 = bM0; lU0 = bU0;
        lM1 = bM1; lU1 = bU1;
    } else if (lane == 31) {
        rM0 = bM0; rU0 = bU0;
        rM1 = bM1; rU1 = bU1;
    }

    float4 res0 = row_result(m0, u0, lM0, lU0, rM0, rU0, mMm, uMm, m1, u1);
    float4 res1 = row_result(m1, u1, lM1, lU1, rM1, rU1, m0, u0, m2, u2);

    float* outI = out + base;
    *reinterpret_cast<float4*>(outI + ((size_t)h0 << 10) + wb) = res0;
    *reinterpret_cast<float4*>(outI + ((size_t)h1 << 10) + wb) = res1;
}

extern "C" void kernel_launch(void* const* d_in, const int* in_sizes, int n_in,
                              void* d_out, int out_size)
{
    const float* M  = (const float*)d_in[0];
    const float* mu = (const float*)d_in[1];
    float* out = (float*)d_out;

    const int grid = N_IMG * (H_DIM / 2);  // 8192 blocks, one row-pair each
    div_grad_kernel<<<grid, 256>>>(M, mu, out);
}

// round 4
// speedup vs baseline: 1.1783x; 1.0597x over previous
#include <cuda_runtime.h>

// Divergence of (average(M) * gradient(mu)) with periodic boundaries.
// Shapes: (B=16, C=1, H=1024, W=1024) fp32.
// out[p] = sum_ax [ v_ax(p) - v_ax(p - e_ax) ],  v_ax(p) = 0.5*(M[p+e]+M[p])*(mu[p+e]-mu[p])
//
// Each thread produces a 4(row) x 4(col float4) strip. Rows h-1..h+4 are
// loaded once (12 float4 loads, all independent -> high MLP) and serve 4
// output rows. Horizontal halos via warp shuffle; lane 0/31 load one
// wrap-aware scalar per row per array, issued before the vector loads.

#define H_DIM 1024
#define W_DIM 1024
#define N_IMG 16

__device__ __forceinline__ float4 row_result(
    const float4 m, const float4 u,
    float mL, float uL, float mR, float uR,
    const float4 mup, const float4 uup,
    const float4 mdn, const float4 udn)
{
    // W-direction forward fluxes (backward flux of elem e == forward of e-1)
    float vm = 0.5f * (m.x + mL)  * (u.x - uL);
    float v0 = 0.5f * (m.y + m.x) * (u.y - u.x);
    float v1 = 0.5f * (m.z + m.y) * (u.z - u.y);
    float v2 = 0.5f * (m.w + m.z) * (u.w - u.z);
    float v3 = 0.5f * (mR  + m.w) * (uR  - u.w);

    float4 r;
    r.x = (v0 - vm) + 0.5f * (mdn.x + m.x) * (udn.x - u.x) - 0.5f * (m.x + mup.x) * (u.x - uup.x);
    r.y = (v1 - v0) + 0.5f * (mdn.y + m.y) * (udn.y - u.y) - 0.5f * (m.y + mup.y) * (u.y - uup.y);
    r.z = (v2 - v1) + 0.5f * (mdn.z + m.z) * (udn.z - u.z) - 0.5f * (m.z + mup.z) * (u.z - uup.z);
    r.w = (v3 - v2) + 0.5f * (mdn.w + m.w) * (udn.w - u.w) - 0.5f * (m.w + mup.w) * (u.w - uup.w);
    return r;
}

__global__ __launch_bounds__(256, 3) void div_grad_kernel(
    const float* __restrict__ M,
    const float* __restrict__ mu,
    float* __restrict__ out)
{
    const int w4   = threadIdx.x;          // 0..255 : float4 column
    const int lane = threadIdx.x & 31;
    const int quad = blockIdx.x & 255;     // 4-row strip index
    const int img  = blockIdx.x >> 8;

    const int h0 = quad << 2;              // 0..1020
    const size_t base = (size_t)img << 20;
    const float* Mi = M  + base;
    const float* Ui = mu + base;
    const int wb = w4 << 2;

    // Row indices: 0 = h0-1 (wrap), 1..4 = h0..h0+3 (no wrap), 5 = h0+4 (wrap)
    int hrow[6];
    hrow[0] = (h0 - 1) & (H_DIM - 1);
    hrow[1] = h0; hrow[2] = h0 + 1; hrow[3] = h0 + 2; hrow[4] = h0 + 3;
    hrow[5] = (h0 + 4) & (H_DIM - 1);

    const float* Mr[6];
    const float* Ur[6];
    #pragma unroll
    for (int i = 0; i < 6; ++i) {
        Mr[i] = Mi + ((size_t)hrow[i] << 10);
        Ur[i] = Ui + ((size_t)hrow[i] << 10);
    }

    // Boundary-lane halo scalars issued FIRST (overlap with vector loads).
    float bM[4], bU[4];
    if (lane == 0) {
        const int wl = (wb - 1) & (W_DIM - 1);
        #pragma unroll
        for (int r = 0; r < 4; ++r) { bM[r] = Mr[r + 1][wl]; bU[r] = Ur[r + 1][wl]; }
    } else if (lane == 31) {
        const int wr = (wb + 4) & (W_DIM - 1);
        #pragma unroll
        for (int r = 0; r < 4; ++r) { bM[r] = Mr[r + 1][wr]; bU[r] = Ur[r + 1][wr]; }
    } else {
        #pragma unroll
        for (int r = 0; r < 4; ++r) { bM[r] = 0.f; bU[r] = 0.f; }
    }

    // 12 independent vector loads
    float4 m[6], u[6];
    #pragma unroll
    for (int i = 0; i < 6; ++i) m[i] = *reinterpret_cast<const float4*>(Mr[i] + wb);
    #pragma unroll
    for (int i = 0; i < 6; ++i) u[i] = *reinterpret_cast<const float4*>(Ur[i] + wb);

    // Horizontal halos via shuffle for the 4 center rows.
    const unsigned FULL = 0xffffffffu;
    float lM[4], lU[4], rM[4], rU[4];
    #pragma unroll
    for (int r = 0; r < 4; ++r) {
        lM[r] = __shfl_up_sync(FULL, m[r + 1].w, 1);
        lU[r] = __shfl_up_sync(FULL, u[r + 1].w, 1);
        rM[r] = __shfl_down_sync(FULL, m[r + 1].x, 1);
        rU[r] = __shfl_down_sync(FULL, u[r + 1].x, 1);
    }
    if (lane == 0) {
        #pragma unroll
        for (int r = 0; r < 4; ++r) { lM[r] = bM[r]; lU[r] = bU[r]; }
    } else if (lane == 31) {
        #pragma unroll
        for (int r = 0; r < 4; ++r) { rM[r] = bM[r]; rU[r] = bU[r]; }
    }

    float* outI = out + base;
    #pragma unroll
    for (int r = 0; r < 4; ++r) {
        float4 res = row_result(m[r + 1], u[r + 1],
                                lM[r], lU[r], rM[r], rU[r],
                                m[r], u[r], m[r + 2], u[r + 2]);
        *reinterpret_cast<float4*>(outI + ((size_t)(h0 + r) << 10) + wb) = res;
    }
}

extern "C" void kernel_launch(void* const* d_in, const int* in_sizes, int n_in,
                              void* d_out, int out_size)
{
    const float* M  = (const float*)d_in[0];
    const float* mu = (const float*)d_in[1];
    float* out = (float*)d_out;

    const int grid = N_IMG * (H_DIM / 4);  // 4096 blocks, one 4-row strip each
    div_grad_kernel<<<grid, 256>>>(M, mu, out);
}